// round 14
// baseline (speedup 1.0000x reference)
#include <cuda_runtime.h>
#include <cuda_fp16.h>
#include <math.h>

// Problem constants: B=16, N=M=512, VS=2048, QS=1024, OS=2048, H=16, DH=128
#define ROWS      8192
#define TRANS_W   6144
#define OS_W      2048

// -------------------- fp16 scratch (device globals; no allocations) --------
__device__ __half gh_v     [(size_t)ROWS * 2048];
__device__ __half gh_q     [(size_t)ROWS * 1024];
__device__ __half gh_Wv    [(size_t)2048 * TRANS_W];   // pair-interleaved
__device__ __half gh_Wq    [(size_t)1024 * TRANS_W];   // pair-interleaved
__device__ __half gh_Wvo   [(size_t)4096 * OS_W];      // pair-interleaved
__device__ __half gh_Wqo   [(size_t)3072 * OS_W];      // pair-interleaved
__device__ __half gh_vtrans[(size_t)ROWS * TRANS_W];
__device__ __half gh_qtrans[(size_t)ROWS * TRANS_W];
__device__ __half gh_vupd  [(size_t)ROWS * OS_W];
__device__ __half gh_qupd  [(size_t)ROWS * OS_W];

__device__ __forceinline__ unsigned pack_h2(float lo, float hi) {
    __half2 h = __floats2half2_rn(lo, hi);
    return *(unsigned*)&h;
}

__device__ __forceinline__ void mma_f16(float c[4], const unsigned a[4], const unsigned b[2]) {
    asm volatile(
        "mma.sync.aligned.m16n8k16.row.col.f32.f16.f16.f32 "
        "{%0,%1,%2,%3}, {%4,%5,%6,%7}, {%8,%9}, {%0,%1,%2,%3};\n"
        : "+f"(c[0]), "+f"(c[1]), "+f"(c[2]), "+f"(c[3])
        : "r"(a[0]), "r"(a[1]), "r"(a[2]), "r"(a[3]),
          "r"(b[0]), "r"(b[1]));
}

__device__ __forceinline__ void cp_async8(unsigned saddr, const void* gaddr) {
    asm volatile("cp.async.ca.shared.global [%0], [%1], 8;"
                 :: "r"(saddr), "l"(gaddr) : "memory");
}
__device__ __forceinline__ void cp_commit() {
    asm volatile("cp.async.commit_group;" ::: "memory");
}
__device__ __forceinline__ void cp_wait2() {
    asm volatile("cp.async.wait_group 2;" ::: "memory");
}

// ============================================================================
// prep: fp32->fp16 for activations (v,q) in one launch
//   v 4194304 f4 | q 2097152 f4 ; total 6291456 = 24576 blocks x 256
// ============================================================================
#define FC0 4194304
#define F2H2_BLOCKS 24576
__global__ void __launch_bounds__(256)
f2h2_kernel(const float* __restrict__ s0, const float* __restrict__ s1,
            __half* __restrict__ d0, __half* __restrict__ d1)
{
    int i = blockIdx.x * blockDim.x + threadIdx.x;
    const float* s; __half* d; int j;
    if (i < FC0) { s = s0; d = d0; j = i; }
    else         { s = s1; d = d1; j = i - FC0; }
    float4 v = ((const float4*)s)[j];
    ((__half2*)d)[2 * j]     = __floats2half2_rn(v.x, v.y);
    ((__half2*)d)[2 * j + 1] = __floats2half2_rn(v.z, v.w);
}

// weight pack: src[Kr][N] fp32 -> dst pair-interleaved:
//   dst_u32[pr*N + c] = half2(src[2pr][c], src[2pr+1][c])
__global__ void __launch_bounds__(256)
wpack_kernel(const float* __restrict__ s, unsigned* __restrict__ d, int Kr, int N, int total)
{
    int i = blockIdx.x * blockDim.x + threadIdx.x;   // over (Kr/2)*(N/4)
    if (i >= total) return;
    int n4 = N >> 2;
    int pr = i / n4, c = (i - pr * n4) << 2;
    float4 lo = *(const float4*)(s + (size_t)(2 * pr)     * N + c);
    float4 hi = *(const float4*)(s + (size_t)(2 * pr + 1) * N + c);
    uint4 u = { pack_h2(lo.x, hi.x), pack_h2(lo.y, hi.y),
                pack_h2(lo.z, hi.z), pack_h2(lo.w, hi.w) };
    *(uint4*)(d + (size_t)pr * N + c) = u;
}

// ============================================================================
// FP16 GEMM, 512 threads (16 warps, 32x32 warp tiles), CTA 128x128, BK=16,
// 4-stage cp.async pipeline, dual-A concat, blockIdx.z selects fused problem.
// B is pre-pair-interleaved (raw copies). acc 32 regs -> 2 CTAs/SM (8 w/SMSP).
// ============================================================================
#define BM 128
#define BN 128
#define NSTAGE 4
#define ASTRIDE 12
#define BSTRIDE 136

struct GemmArgs {
    const __half* A1; const __half* A2; const unsigned* B;
    float* C32; __half* C16;
    const float* bias; const float* mask;
    int K1; int K2;
};

__global__ void __launch_bounds__(512, 2)
hgemm16_kernel(GemmArgs ga, GemmArgs gb, int N)
{
    const GemmArgs g = blockIdx.z ? gb : ga;
    const int K1 = g.K1, K2 = g.K2;
    const int K = K1 + K2;
    const int nCh = K >> 4;

    __shared__ unsigned As[NSTAGE][BM][ASTRIDE];
    __shared__ unsigned Bs[NSTAGE][8][BSTRIDE];

    const int tid  = threadIdx.x;
    const int lane = tid & 31;
    const int warp = tid >> 5;           // 0..15
    const int gid  = lane >> 2;
    const int tig  = lane & 3;
    const int wm = (warp >> 2) * 32;     // 0,32,64,96
    const int wn = (warp & 3) * 32;      // 0,32,64,96

    const int rowBase = blockIdx.y * BM;
    const int colBase = blockIdx.x * BN;

    // A staging: thread -> row aR (0..127), 8B at half-offset aH (0/4/8/12)
    const int aR = tid >> 2;
    const int aH = (tid & 3) << 2;
    // B staging: thread -> pair-row pr (0..7), 8B (2 cols) at col bc
    const int pr = tid >> 6;
    const int bc = (tid & 63) << 1;

    const __half* pa1 = (K1 > 0) ? g.A1 + (size_t)(rowBase + aR) * K1 + aH : nullptr;
    const __half* pa2 = (K2 > 0) ? g.A2 + (size_t)(rowBase + aR) * K2 - K1 + aH : nullptr;
    if (!pa1) pa1 = pa2;
    if (!pa2) pa2 = pa1;
    const unsigned* pb = g.B + (size_t)pr * N + colBase + bc;

    unsigned aDst, bDst;
    {
        unsigned long long t;
        asm("cvta.to.shared.u64 %0, %1;" : "=l"(t) : "l"((void*)&As[0][aR][aH >> 1]));
        aDst = (unsigned)t;
        asm("cvta.to.shared.u64 %0, %1;" : "=l"(t) : "l"((void*)&Bs[0][pr][bc]));
        bDst = (unsigned)t;
    }
    const unsigned aStB = BM * ASTRIDE * 4;
    const unsigned bStB = 8 * BSTRIDE * 4;

    float acc[2][4][4];
#pragma unroll
    for (int i = 0; i < 2; i++)
#pragma unroll
        for (int j = 0; j < 4; j++)
#pragma unroll
            for (int r = 0; r < 4; r++) acc[i][j][r] = 0.0f;

    // prologue: chunks 0..2
#pragma unroll
    for (int p = 0; p < 3; p++) {
        const int k0 = p << 4;
        const __half* s = ((k0 < K1) ? pa1 : pa2) + k0;
        cp_async8(aDst + (unsigned)p * aStB, s);
        cp_async8(bDst + (unsigned)p * bStB, pb + (size_t)(k0 >> 1) * N);
        cp_commit();
    }

    for (int ck = 0; ck < nCh; ck++) {
        cp_wait2();
        __syncthreads();
        const int st = ck & 3;

        unsigned afr[2][4];
#pragma unroll
        for (int mt = 0; mt < 2; mt++) {
            const int r = wm + mt * 16 + gid;
            afr[mt][0] = As[st][r][tig];
            afr[mt][1] = As[st][r + 8][tig];
            afr[mt][2] = As[st][r][tig + 4];
            afr[mt][3] = As[st][r + 8][tig + 4];
        }
        unsigned bfr[4][2];
#pragma unroll
        for (int nt = 0; nt < 4; nt++) {
            const int c = wn + nt * 8 + gid;
            bfr[nt][0] = Bs[st][tig][c];
            bfr[nt][1] = Bs[st][tig + 4][c];
        }
#pragma unroll
        for (int mt = 0; mt < 2; mt++)
#pragma unroll
            for (int nt = 0; nt < 4; nt++)
                mma_f16(acc[mt][nt], afr[mt], bfr[nt]);

        // issue chunk ck+3 into stage (ck+3)&3 == (ck-1)&3 (safe: sync above
        // guarantees all warps finished computing that stage last iteration)
        const int cn = ck + 3;
        if (cn < nCh) {
            const int k0 = cn << 4;
            const __half* s = ((k0 < K1) ? pa1 : pa2) + k0;
            const unsigned stn = (unsigned)(cn & 3);
            cp_async8(aDst + stn * aStB, s);
            cp_async8(bDst + stn * bStB, pb + (size_t)(k0 >> 1) * N);
        }
        cp_commit();   // keep group count aligned even when no copies
    }

    // ---- epilogue ----
#pragma unroll
    for (int mt = 0; mt < 2; mt++) {
        const int r0 = rowBase + wm + mt * 16 + gid;
        const int r1 = r0 + 8;
        const float m0 = g.mask ? g.mask[r0] : 1.0f;
        const float m1 = g.mask ? g.mask[r1] : 1.0f;
#pragma unroll
        for (int nt = 0; nt < 4; nt++) {
            const int c = colBase + wn + nt * 8 + (tig << 1);
            const float b0 = g.bias[c], b1 = g.bias[c + 1];
            float v00 = fmaxf(acc[mt][nt][0] + b0, 0.0f) * m0;
            float v01 = fmaxf(acc[mt][nt][1] + b1, 0.0f) * m0;
            float v10 = fmaxf(acc[mt][nt][2] + b0, 0.0f) * m1;
            float v11 = fmaxf(acc[mt][nt][3] + b1, 0.0f) * m1;
            if (g.C16) {
                *(__half2*)(g.C16 + (size_t)r0 * N + c) = __floats2half2_rn(v00, v01);
                *(__half2*)(g.C16 + (size_t)r1 * N + c) = __floats2half2_rn(v10, v11);
            } else {
                float2 a = { v00, v01 }, b = { v10, v11 };
                *(float2*)(g.C32 + (size_t)r0 * N + c) = a;
                *(float2*)(g.C32 + (size_t)r1 * N + c) = b;
            }
        }
    }
}

// ============================================================================
// FP16 tensor-core flash attention — unchanged from R13 (passing); both
// directions fused via blockIdx.y in [0,32): dir = y>>4, h = y&15.
// ============================================================================
struct AttnSmem3 {
    unsigned Qh[128][68];
    unsigned Kh[64][68];
    unsigned Vh[32][136];
    unsigned Ps[128][36];
    float    Mk[64];
};

__global__ void __launch_bounds__(256)
attn_mma_kernel(const __half* __restrict__ vtrans, const __half* __restrict__ qtrans,
                const float* __restrict__ vmask, const float* __restrict__ qmask,
                __half* __restrict__ vupd, __half* __restrict__ qupd)
{
    extern __shared__ char smem_raw[];
    AttnSmem3& sm = *reinterpret_cast<AttnSmem3*>(smem_raw);

    const int b   = blockIdx.z;
    const int hd  = blockIdx.y;
    const int dir = hd >> 4;
    const int h   = hd & 15;
    const int qt  = blockIdx.x;

    const __half* Tq    = dir ? qtrans : vtrans;
    const __half* Tk    = dir ? vtrans : qtrans;
    const float*  maskK = dir ? vmask  : qmask;
    __half*       out   = dir ? qupd   : vupd;

    const int tid  = threadIdx.x;
    const int lane = tid & 31;
    const int warp = tid >> 5;
    const int r0   = warp * 16;
    const int gid  = lane >> 2;
    const int tig  = lane & 3;
    const float SCALE = 0.08838834764831845f;

    const __half* qbase = Tq + (size_t)(b * 512 + qt * 128) * 6144 + 2048 + h * 128;
#pragma unroll
    for (int it = 0; it < 8; it++) {
        int lin = it * 256 + tid;
        int r = lin >> 4, cu = (lin & 15) << 2;
        uint4 u = *(const uint4*)(qbase + (size_t)r * 6144 + cu * 2);
        *(uint4*)&sm.Qh[r][cu] = u;
    }

    float m_i[2] = { -INFINITY, -INFINITY };
    float l_i[2] = { 0.0f, 0.0f };
    float oacc[16][4];
#pragma unroll
    for (int nt = 0; nt < 16; nt++)
#pragma unroll
        for (int j = 0; j < 4; j++) oacc[nt][j] = 0.0f;

    const __half* kbase = Tk + (size_t)b * 512 * 6144 + h * 128;
    const __half* vbase = kbase + 4096;

    const int vpr = tid >> 5;
    const int vc0 = (tid & 31) << 2;

    for (int kt = 0; kt < 8; kt++) {
        __syncthreads();
#pragma unroll
        for (int it = 0; it < 4; it++) {
            int lin = it * 256 + tid;
            int r = lin >> 4, cu = (lin & 15) << 2;
            uint4 u = *(const uint4*)(kbase + (size_t)(kt * 64 + r) * 6144 + cu * 2);
            *(uint4*)&sm.Kh[r][cu] = u;
        }
#pragma unroll
        for (int it = 0; it < 4; it++) {
            int p = it * 8 + vpr;
            uint2 lo = *(const uint2*)(vbase + (size_t)(kt * 64 + 2 * p)     * 6144 + vc0);
            uint2 hi = *(const uint2*)(vbase + (size_t)(kt * 64 + 2 * p + 1) * 6144 + vc0);
            uint4 u;
            u.x = __byte_perm(lo.x, hi.x, 0x5410);
            u.y = __byte_perm(lo.x, hi.x, 0x7632);
            u.z = __byte_perm(lo.y, hi.y, 0x5410);
            u.w = __byte_perm(lo.y, hi.y, 0x7632);
            *(uint4*)&sm.Vh[p][vc0] = u;
        }
        if (tid < 64) sm.Mk[tid] = maskK[b * 512 + kt * 64 + tid];
        __syncthreads();

        float c[8][4];
#pragma unroll
        for (int nt = 0; nt < 8; nt++)
#pragma unroll
            for (int j = 0; j < 4; j++) c[nt][j] = 0.0f;

#pragma unroll
        for (int ks = 0; ks < 8; ks++) {
            const int pd = ks * 8 + tig;
            unsigned a[4];
            a[0] = sm.Qh[r0 + gid][pd];
            a[1] = sm.Qh[r0 + gid + 8][pd];
            a[2] = sm.Qh[r0 + gid][pd + 4];
            a[3] = sm.Qh[r0 + gid + 8][pd + 4];
#pragma unroll
            for (int nt = 0; nt < 8; nt++) {
                unsigned bf[2];
                bf[0] = sm.Kh[nt * 8 + gid][pd];
                bf[1] = sm.Kh[nt * 8 + gid][pd + 4];
                mma_f16(c[nt], a, bf);
            }
        }

#pragma unroll
        for (int nt = 0; nt < 8; nt++) {
            const int col = nt * 8 + tig * 2;
            const float k0m = sm.Mk[col];
            const float k1m = sm.Mk[col + 1];
            c[nt][0] = (k0m != 0.0f) ? c[nt][0] * SCALE : -INFINITY;
            c[nt][1] = (k1m != 0.0f) ? c[nt][1] * SCALE : -INFINITY;
            c[nt][2] = (k0m != 0.0f) ? c[nt][2] * SCALE : -INFINITY;
            c[nt][3] = (k1m != 0.0f) ? c[nt][3] * SCALE : -INFINITY;
        }

#pragma unroll
        for (int j = 0; j < 2; j++) {
            float tmax = -INFINITY;
#pragma unroll
            for (int nt = 0; nt < 8; nt++)
                tmax = fmaxf(tmax, fmaxf(c[nt][j * 2], c[nt][j * 2 + 1]));
            tmax = fmaxf(tmax, __shfl_xor_sync(0xffffffffu, tmax, 1));
            tmax = fmaxf(tmax, __shfl_xor_sync(0xffffffffu, tmax, 2));
            float mnew  = fmaxf(m_i[j], tmax);
            float msafe = (mnew == -INFINITY) ? 0.0f : mnew;
            float corr  = __expf(m_i[j] - msafe);
            float lsum = 0.0f;
            const int row = r0 + gid + j * 8;
#pragma unroll
            for (int nt = 0; nt < 8; nt++) {
                float p0 = __expf(c[nt][j * 2]     - msafe);
                float p1 = __expf(c[nt][j * 2 + 1] - msafe);
                lsum += p0 + p1;
                sm.Ps[row][nt * 4 + tig] = pack_h2(p0, p1);
            }
            lsum += __shfl_xor_sync(0xffffffffu, lsum, 1);
            lsum += __shfl_xor_sync(0xffffffffu, lsum, 2);
            l_i[j] = l_i[j] * corr + lsum;
            m_i[j] = mnew;
#pragma unroll
            for (int nt = 0; nt < 16; nt++) {
                oacc[nt][j * 2]     *= corr;
                oacc[nt][j * 2 + 1] *= corr;
            }
        }
        __syncwarp();

#pragma unroll
        for (int ks = 0; ks < 4; ks++) {
            const int pk = ks * 8 + tig;
            unsigned a[4];
            a[0] = sm.Ps[r0 + gid][pk];
            a[1] = sm.Ps[r0 + gid + 8][pk];
            a[2] = sm.Ps[r0 + gid][pk + 4];
            a[3] = sm.Ps[r0 + gid + 8][pk + 4];
#pragma unroll
            for (int nt = 0; nt < 16; nt++) {
                unsigned bf[2];
                bf[0] = sm.Vh[ks * 8 + tig][nt * 8 + gid];
                bf[1] = sm.Vh[ks * 8 + tig + 4][nt * 8 + gid];
                mma_f16(oacc[nt], a, bf);
            }
        }
    }

#pragma unroll
    for (int j = 0; j < 2; j++) {
        const float inv = (l_i[j] > 0.0f) ? (1.0f / l_i[j]) : 0.0f;
        const size_t orow = (size_t)(b * 512 + qt * 128 + r0 + gid + j * 8);
        __half* op = out + orow * 2048 + h * 128 + tig * 2;
#pragma unroll
        for (int nt = 0; nt < 16; nt++) {
            *(__half2*)(op + nt * 8) =
                __floats2half2_rn(oacc[nt][j * 2] * inv, oacc[nt][j * 2 + 1] * inv);
        }
    }
}

// ============================================================================
extern "C" void kernel_launch(void* const* d_in, const int* in_sizes, int n_in,
                              void* d_out, int out_size)
{
    (void)in_sizes; (void)n_in; (void)out_size;
    const float* v     = (const float*)d_in[0];
    const float* q     = (const float*)d_in[1];
    const float* vmask = (const float*)d_in[2];
    const float* qmask = (const float*)d_in[3];
    const float* Wv    = (const float*)d_in[4];
    const float* bv    = (const float*)d_in[5];
    const float* Wq    = (const float*)d_in[6];
    const float* bq    = (const float*)d_in[7];
    const float* Wvo   = (const float*)d_in[8];
    const float* bvo   = (const float*)d_in[9];
    const float* Wqo   = (const float*)d_in[10];
    const float* bqo   = (const float*)d_in[11];

    float* out_v = (float*)d_out;
    float* out_q = out_v + (size_t)ROWS * OS_W;

    __half *vh, *qh, *Wvh, *Wqh, *Wvoh, *Wqoh, *vtrans, *qtrans, *vupd, *qupd;
    cudaGetSymbolAddress((void**)&vh,     gh_v);
    cudaGetSymbolAddress((void**)&qh,     gh_q);
    cudaGetSymbolAddress((void**)&Wvh,    gh_Wv);
    cudaGetSymbolAddress((void**)&Wqh,    gh_Wq);
    cudaGetSymbolAddress((void**)&Wvoh,   gh_Wvo);
    cudaGetSymbolAddress((void**)&Wqoh,   gh_Wqo);
    cudaGetSymbolAddress((void**)&vtrans, gh_vtrans);
    cudaGetSymbolAddress((void**)&qtrans, gh_qtrans);
    cudaGetSymbolAddress((void**)&vupd,   gh_vupd);
    cudaGetSymbolAddress((void**)&qupd,   gh_qupd);

    cudaFuncSetAttribute(attn_mma_kernel, cudaFuncAttributeMaxDynamicSharedMemorySize,
                         (int)sizeof(AttnSmem3));

    dim3 blk(256);
    dim3 blk512(512);

    // 0) activations fp32->fp16 (one launch) + weight pair-interleave packs
    f2h2_kernel<<<F2H2_BLOCKS, blk>>>(v, q, vh, qh);
    wpack_kernel<<<6144, blk>>>(Wv,  (unsigned*)Wvh,  2048, TRANS_W, 1024 * (TRANS_W / 4));
    wpack_kernel<<<3072, blk>>>(Wq,  (unsigned*)Wqh,  1024, TRANS_W,  512 * (TRANS_W / 4));
    wpack_kernel<<<4096, blk>>>(Wvo, (unsigned*)Wvoh, 4096, OS_W,    2048 * (OS_W / 4));
    wpack_kernel<<<3072, blk>>>(Wqo, (unsigned*)Wqoh, 3072, OS_W,    1536 * (OS_W / 4));

    // 1+2) fused: v_trans / q_trans
    {
        GemmArgs ga = { vh, nullptr, (const unsigned*)Wvh, nullptr, vtrans, bv, vmask, 2048, 0 };
        GemmArgs gb = { qh, nullptr, (const unsigned*)Wqh, nullptr, qtrans, bq, qmask, 1024, 0 };
        hgemm16_kernel<<<dim3(TRANS_W / BN, ROWS / BM, 2), blk512>>>(ga, gb, TRANS_W);
    }

    // 3+4) fused bidirectional attention
    attn_mma_kernel<<<dim3(4, 32, 16), blk, sizeof(AttnSmem3)>>>(
        vtrans, qtrans, vmask, qmask, vupd, qupd);

    // 5+6) fused: updated_v / updated_q (concat GEMMs, fp32 out)
    {
        GemmArgs ga = { vh, vupd, (const unsigned*)Wvoh, out_v, nullptr, bvo, nullptr, 2048, 2048 };
        GemmArgs gb = { qh, qupd, (const unsigned*)Wqoh, out_q, nullptr, bqo, nullptr, 1024, 2048 };
        hgemm16_kernel<<<dim3(OS_W / BN, ROWS / BM, 2), blk512>>>(ga, gb, OS_W);
    }
}

// round 15
// speedup vs baseline: 1.2525x; 1.2525x over previous
#include <cuda_runtime.h>
#include <cuda_fp16.h>
#include <math.h>

// Problem constants: B=16, N=M=512, VS=2048, QS=1024, OS=2048, H=16, DH=128
#define ROWS      8192
#define TRANS_W   6144
#define OS_W      2048

// -------------------- fp16 scratch (device globals; no allocations) --------
__device__ __half gh_v     [(size_t)ROWS * 2048];
__device__ __half gh_q     [(size_t)ROWS * 1024];
__device__ __half gh_Wv    [(size_t)2048 * TRANS_W];
__device__ __half gh_Wq    [(size_t)1024 * TRANS_W];
__device__ __half gh_Wvo   [(size_t)4096 * OS_W];
__device__ __half gh_Wqo   [(size_t)3072 * OS_W];
__device__ __half gh_vtrans[(size_t)ROWS * TRANS_W];
__device__ __half gh_qtrans[(size_t)ROWS * TRANS_W];
__device__ __half gh_vupd  [(size_t)ROWS * OS_W];
__device__ __half gh_qupd  [(size_t)ROWS * OS_W];

__device__ __forceinline__ unsigned pack_h2(float lo, float hi) {
    __half2 h = __floats2half2_rn(lo, hi);
    return *(unsigned*)&h;
}

__device__ __forceinline__ void mma_f16(float c[4], const unsigned a[4], const unsigned b[2]) {
    asm volatile(
        "mma.sync.aligned.m16n8k16.row.col.f32.f16.f16.f32 "
        "{%0,%1,%2,%3}, {%4,%5,%6,%7}, {%8,%9}, {%0,%1,%2,%3};\n"
        : "+f"(c[0]), "+f"(c[1]), "+f"(c[2]), "+f"(c[3])
        : "r"(a[0]), "r"(a[1]), "r"(a[2]), "r"(a[3]),
          "r"(b[0]), "r"(b[1]));
}

// ============================================================================
// fused fp32 -> fp16 conversion over all 6 tensors (one launch) — R13 proven
// ============================================================================
#define C0 4194304
#define C1 6291456
#define C2 9437184
#define C3 11010048
#define C4 13107200
#define CONV_BLOCKS 57344

__global__ void __launch_bounds__(256)
f2h6_kernel(const float* __restrict__ s0, const float* __restrict__ s1,
            const float* __restrict__ s2, const float* __restrict__ s3,
            const float* __restrict__ s4, const float* __restrict__ s5,
            __half* __restrict__ d0, __half* __restrict__ d1,
            __half* __restrict__ d2, __half* __restrict__ d3,
            __half* __restrict__ d4, __half* __restrict__ d5)
{
    int i = blockIdx.x * blockDim.x + threadIdx.x;
    const float* s; __half* d; int off;
    if (i < C0)      { s = s0; d = d0; off = 0;  }
    else if (i < C1) { s = s1; d = d1; off = C0; }
    else if (i < C2) { s = s2; d = d2; off = C1; }
    else if (i < C3) { s = s3; d = d3; off = C2; }
    else if (i < C4) { s = s4; d = d4; off = C3; }
    else             { s = s5; d = d5; off = C4; }
    int j = i - off;
    float4 v = ((const float4*)s)[j];
    ((__half2*)d)[2 * j]     = __floats2half2_rn(v.x, v.y);
    ((__half2*)d)[2 * j + 1] = __floats2half2_rn(v.z, v.w);
}

// ============================================================================
// FP16-in GEMM (fp32 accum) — R13 core with BK=32 (two k16 steps per barrier).
// CTA 128x128, warp 64x32, double-buffered, dual-A concat, z-fused problems.
//   As[stage][128][20]  u32 k-pairs; row stride 20 -> a-frag conflict-free
//   Bs[stage][16][136]  u32 key-pairs (PRMT interleaved); b-frag conflict-free
// ============================================================================
#define BM 128
#define BN 128
#define BK 32
#define ASTRIDE 20
#define BSTRIDE 136

struct GemmArgs {
    const __half* A1; const __half* A2; const __half* B;
    float* C32; __half* C16;
    const float* bias; const float* mask;
    int K1; int K2;
};

__global__ void __launch_bounds__(256, 2)
hgemm16_kernel(GemmArgs ga, GemmArgs gb, int N)
{
    const GemmArgs g = blockIdx.z ? gb : ga;
    const __half* __restrict__ A1 = g.A1;
    const __half* __restrict__ A2 = g.A2;
    const __half* __restrict__ Bm = g.B;
    float*  __restrict__ C32 = g.C32;
    __half* __restrict__ C16 = g.C16;
    const float* __restrict__ bias = g.bias;
    const float* __restrict__ mask = g.mask;
    const int K1 = g.K1, K2 = g.K2;

    __shared__ unsigned As[2][BM][ASTRIDE];
    __shared__ unsigned Bs[2][16][BSTRIDE];

    const int tid  = threadIdx.x;
    const int lane = tid & 31;
    const int warp = tid >> 5;
    const int gid  = lane >> 2;
    const int tig  = lane & 3;
    const int wm = (warp >> 2) * 64;
    const int wn = (warp & 3) * 32;

    const int rowBase = blockIdx.y * BM;
    const int colBase = blockIdx.x * BN;

    // A staging: thread -> rows aR0, aR0+64; uint4 (8 halves) at half-off aH
    const int aR0 = tid >> 2;          // 0..63
    const int q4  = tid & 3;           // uint4 slot in row (0..3)
    const int aH  = q4 * 8;            // half offset 0/8/16/24
    const int aR1 = aR0 + 64;
    // B staging: thread -> pair-rows pr0, pr0+8; 4 cols at c4
    const int pr0 = tid >> 5;          // 0..7
    const int c4  = (tid & 31) << 2;   // 0..124

    const int K = K1 + K2;
    const int kChunks = K / BK;

    const __half* P1r0 = (K1 > 0) ? A1 + (size_t)(rowBase + aR0) * K1 + aH : nullptr;
    const __half* P1r1 = (K1 > 0) ? A1 + (size_t)(rowBase + aR1) * K1 + aH : nullptr;
    const __half* P2r0 = (K2 > 0) ? A2 + (size_t)(rowBase + aR0) * K2 - K1 + aH : nullptr;
    const __half* P2r1 = (K2 > 0) ? A2 + (size_t)(rowBase + aR1) * K2 - K1 + aH : nullptr;

    // single B base; per-chunk offsets derived (rows 2pr0, 2pr0+1, +16, +17)
    const __half* pB = Bm + (size_t)(2 * pr0) * N + colBase + c4;

    float acc[4][4][4];
#pragma unroll
    for (int i = 0; i < 4; i++)
#pragma unroll
        for (int j = 0; j < 4; j++)
#pragma unroll
            for (int r = 0; r < 4; r++) acc[i][j][r] = 0.0f;

    // ---- prologue: prefetch chunk 0 ----
    uint4 ra0, ra1;
    uint2 rbl0, rbh0, rbl1, rbh1;
    {
        const __half* s0 = (0 < K1) ? P1r0 : P2r0;
        const __half* s1 = (0 < K1) ? P1r1 : P2r1;
        ra0 = *(const uint4*)s0;
        ra1 = *(const uint4*)s1;
        rbl0 = *(const uint2*)pB;
        rbh0 = *(const uint2*)(pB + N);
        rbl1 = *(const uint2*)(pB + 16 * (size_t)N);
        rbh1 = *(const uint2*)(pB + 17 * (size_t)N);
    }

    for (int ck = 0; ck < kChunks; ck++) {
        const int cur = ck & 1;

        // A: raw uint4 copy (k-pairs contiguous)
        *(uint4*)&As[cur][aR0][q4 * 4] = ra0;
        *(uint4*)&As[cur][aR1][q4 * 4] = ra1;
        // B: PRMT interleave rows (2pr,2pr+1) per column
        {
            uint4 u;
            u.x = __byte_perm(rbl0.x, rbh0.x, 0x5410);
            u.y = __byte_perm(rbl0.x, rbh0.x, 0x7632);
            u.z = __byte_perm(rbl0.y, rbh0.y, 0x5410);
            u.w = __byte_perm(rbl0.y, rbh0.y, 0x7632);
            *(uint4*)&Bs[cur][pr0][c4] = u;
            u.x = __byte_perm(rbl1.x, rbh1.x, 0x5410);
            u.y = __byte_perm(rbl1.x, rbh1.x, 0x7632);
            u.z = __byte_perm(rbl1.y, rbh1.y, 0x5410);
            u.w = __byte_perm(rbl1.y, rbh1.y, 0x7632);
            *(uint4*)&Bs[cur][pr0 + 8][c4] = u;
        }
        __syncthreads();

        // prefetch next chunk
        if (ck + 1 < kChunks) {
            const int k0n = (ck + 1) * BK;
            const __half* s0 = (k0n < K1) ? P1r0 : P2r0;
            const __half* s1 = (k0n < K1) ? P1r1 : P2r1;
            ra0 = *(const uint4*)(s0 + k0n);
            ra1 = *(const uint4*)(s1 + k0n);
            const __half* pb = pB + (size_t)k0n * N;
            rbl0 = *(const uint2*)pb;
            rbh0 = *(const uint2*)(pb + N);
            rbl1 = *(const uint2*)(pb + 16 * (size_t)N);
            rbh1 = *(const uint2*)(pb + 17 * (size_t)N);
        }

        // compute: two k16 steps, 16 MMAs each
#pragma unroll
        for (int ks = 0; ks < 2; ks++) {
            const int o = ks * 8;
            unsigned afr[4][4];
#pragma unroll
            for (int mt = 0; mt < 4; mt++) {
                const int r = wm + mt * 16 + gid;
                afr[mt][0] = As[cur][r][o + tig];
                afr[mt][1] = As[cur][r + 8][o + tig];
                afr[mt][2] = As[cur][r][o + tig + 4];
                afr[mt][3] = As[cur][r + 8][o + tig + 4];
            }
            unsigned bfr[4][2];
#pragma unroll
            for (int nt = 0; nt < 4; nt++) {
                const int c = wn + nt * 8 + gid;
                bfr[nt][0] = Bs[cur][o + tig][c];
                bfr[nt][1] = Bs[cur][o + tig + 4][c];
            }
#pragma unroll
            for (int mt = 0; mt < 4; mt++)
#pragma unroll
                for (int nt = 0; nt < 4; nt++)
                    mma_f16(acc[mt][nt], afr[mt], bfr[nt]);
        }
        // single sync per chunk: next store targets the other stage
    }

    // ---- epilogue: relu(x + bias[col]) * mask[row]; fp16 or fp32 out ----
#pragma unroll
    for (int mt = 0; mt < 4; mt++) {
        const int r0 = rowBase + wm + mt * 16 + gid;
        const int r1 = r0 + 8;
        const float m0 = mask ? mask[r0] : 1.0f;
        const float m1 = mask ? mask[r1] : 1.0f;
#pragma unroll
        for (int nt = 0; nt < 4; nt++) {
            const int c = colBase + wn + nt * 8 + (tig << 1);
            const float b0 = bias[c], b1 = bias[c + 1];
            float v00 = fmaxf(acc[mt][nt][0] + b0, 0.0f) * m0;
            float v01 = fmaxf(acc[mt][nt][1] + b1, 0.0f) * m0;
            float v10 = fmaxf(acc[mt][nt][2] + b0, 0.0f) * m1;
            float v11 = fmaxf(acc[mt][nt][3] + b1, 0.0f) * m1;
            if (C16) {
                *(__half2*)(C16 + (size_t)r0 * N + c) = __floats2half2_rn(v00, v01);
                *(__half2*)(C16 + (size_t)r1 * N + c) = __floats2half2_rn(v10, v11);
            } else {
                float2 a = { v00, v01 }, b = { v10, v11 };
                *(float2*)(C32 + (size_t)r0 * N + c) = a;
                *(float2*)(C32 + (size_t)r1 * N + c) = b;
            }
        }
    }
}

// ============================================================================
// FP16 tensor-core flash attention — unchanged from R13 (passing); both
// directions fused via blockIdx.y in [0,32): dir = y>>4, h = y&15.
// ============================================================================
struct AttnSmem3 {
    unsigned Qh[128][68];
    unsigned Kh[64][68];
    unsigned Vh[32][136];
    unsigned Ps[128][36];
    float    Mk[64];
};

__global__ void __launch_bounds__(256)
attn_mma_kernel(const __half* __restrict__ vtrans, const __half* __restrict__ qtrans,
                const float* __restrict__ vmask, const float* __restrict__ qmask,
                __half* __restrict__ vupd, __half* __restrict__ qupd)
{
    extern __shared__ char smem_raw[];
    AttnSmem3& sm = *reinterpret_cast<AttnSmem3*>(smem_raw);

    const int b   = blockIdx.z;
    const int hd  = blockIdx.y;
    const int dir = hd >> 4;
    const int h   = hd & 15;
    const int qt  = blockIdx.x;

    const __half* Tq    = dir ? qtrans : vtrans;
    const __half* Tk    = dir ? vtrans : qtrans;
    const float*  maskK = dir ? vmask  : qmask;
    __half*       out   = dir ? qupd   : vupd;

    const int tid  = threadIdx.x;
    const int lane = tid & 31;
    const int warp = tid >> 5;
    const int r0   = warp * 16;
    const int gid  = lane >> 2;
    const int tig  = lane & 3;
    const float SCALE = 0.08838834764831845f;

    const __half* qbase = Tq + (size_t)(b * 512 + qt * 128) * 6144 + 2048 + h * 128;
#pragma unroll
    for (int it = 0; it < 8; it++) {
        int lin = it * 256 + tid;
        int r = lin >> 4, cu = (lin & 15) << 2;
        uint4 u = *(const uint4*)(qbase + (size_t)r * 6144 + cu * 2);
        *(uint4*)&sm.Qh[r][cu] = u;
    }

    float m_i[2] = { -INFINITY, -INFINITY };
    float l_i[2] = { 0.0f, 0.0f };
    float oacc[16][4];
#pragma unroll
    for (int nt = 0; nt < 16; nt++)
#pragma unroll
        for (int j = 0; j < 4; j++) oacc[nt][j] = 0.0f;

    const __half* kbase = Tk + (size_t)b * 512 * 6144 + h * 128;
    const __half* vbase = kbase + 4096;

    const int vpr = tid >> 5;
    const int vc0 = (tid & 31) << 2;

    for (int kt = 0; kt < 8; kt++) {
        __syncthreads();
#pragma unroll
        for (int it = 0; it < 4; it++) {
            int lin = it * 256 + tid;
            int r = lin >> 4, cu = (lin & 15) << 2;
            uint4 u = *(const uint4*)(kbase + (size_t)(kt * 64 + r) * 6144 + cu * 2);
            *(uint4*)&sm.Kh[r][cu] = u;
        }
#pragma unroll
        for (int it = 0; it < 4; it++) {
            int p = it * 8 + vpr;
            uint2 lo = *(const uint2*)(vbase + (size_t)(kt * 64 + 2 * p)     * 6144 + vc0);
            uint2 hi = *(const uint2*)(vbase + (size_t)(kt * 64 + 2 * p + 1) * 6144 + vc0);
            uint4 u;
            u.x = __byte_perm(lo.x, hi.x, 0x5410);
            u.y = __byte_perm(lo.x, hi.x, 0x7632);
            u.z = __byte_perm(lo.y, hi.y, 0x5410);
            u.w = __byte_perm(lo.y, hi.y, 0x7632);
            *(uint4*)&sm.Vh[p][vc0] = u;
        }
        if (tid < 64) sm.Mk[tid] = maskK[b * 512 + kt * 64 + tid];
        __syncthreads();

        float c[8][4];
#pragma unroll
        for (int nt = 0; nt < 8; nt++)
#pragma unroll
            for (int j = 0; j < 4; j++) c[nt][j] = 0.0f;

#pragma unroll
        for (int ks = 0; ks < 8; ks++) {
            const int pd = ks * 8 + tig;
            unsigned a[4];
            a[0] = sm.Qh[r0 + gid][pd];
            a[1] = sm.Qh[r0 + gid + 8][pd];
            a[2] = sm.Qh[r0 + gid][pd + 4];
            a[3] = sm.Qh[r0 + gid + 8][pd + 4];
#pragma unroll
            for (int nt = 0; nt < 8; nt++) {
                unsigned bf[2];
                bf[0] = sm.Kh[nt * 8 + gid][pd];
                bf[1] = sm.Kh[nt * 8 + gid][pd + 4];
                mma_f16(c[nt], a, bf);
            }
        }

#pragma unroll
        for (int nt = 0; nt < 8; nt++) {
            const int col = nt * 8 + tig * 2;
            const float k0m = sm.Mk[col];
            const float k1m = sm.Mk[col + 1];
            c[nt][0] = (k0m != 0.0f) ? c[nt][0] * SCALE : -INFINITY;
            c[nt][1] = (k1m != 0.0f) ? c[nt][1] * SCALE : -INFINITY;
            c[nt][2] = (k0m != 0.0f) ? c[nt][2] * SCALE : -INFINITY;
            c[nt][3] = (k1m != 0.0f) ? c[nt][3] * SCALE : -INFINITY;
        }

#pragma unroll
        for (int j = 0; j < 2; j++) {
            float tmax = -INFINITY;
#pragma unroll
            for (int nt = 0; nt < 8; nt++)
                tmax = fmaxf(tmax, fmaxf(c[nt][j * 2], c[nt][j * 2 + 1]));
            tmax = fmaxf(tmax, __shfl_xor_sync(0xffffffffu, tmax, 1));
            tmax = fmaxf(tmax, __shfl_xor_sync(0xffffffffu, tmax, 2));
            float mnew  = fmaxf(m_i[j], tmax);
            float msafe = (mnew == -INFINITY) ? 0.0f : mnew;
            float corr  = __expf(m_i[j] - msafe);
            float lsum = 0.0f;
            const int row = r0 + gid + j * 8;
#pragma unroll
            for (int nt = 0; nt < 8; nt++) {
                float p0 = __expf(c[nt][j * 2]     - msafe);
                float p1 = __expf(c[nt][j * 2 + 1] - msafe);
                lsum += p0 + p1;
                sm.Ps[row][nt * 4 + tig] = pack_h2(p0, p1);
            }
            lsum += __shfl_xor_sync(0xffffffffu, lsum, 1);
            lsum += __shfl_xor_sync(0xffffffffu, lsum, 2);
            l_i[j] = l_i[j] * corr + lsum;
            m_i[j] = mnew;
#pragma unroll
            for (int nt = 0; nt < 16; nt++) {
                oacc[nt][j * 2]     *= corr;
                oacc[nt][j * 2 + 1] *= corr;
            }
        }
        __syncwarp();

#pragma unroll
        for (int ks = 0; ks < 4; ks++) {
            const int pk = ks * 8 + tig;
            unsigned a[4];
            a[0] = sm.Ps[r0 + gid][pk];
            a[1] = sm.Ps[r0 + gid + 8][pk];
            a[2] = sm.Ps[r0 + gid][pk + 4];
            a[3] = sm.Ps[r0 + gid + 8][pk + 4];
#pragma unroll
            for (int nt = 0; nt < 16; nt++) {
                unsigned bf[2];
                bf[0] = sm.Vh[ks * 8 + tig][nt * 8 + gid];
                bf[1] = sm.Vh[ks * 8 + tig + 4][nt * 8 + gid];
                mma_f16(oacc[nt], a, bf);
            }
        }
    }

#pragma unroll
    for (int j = 0; j < 2; j++) {
        const float inv = (l_i[j] > 0.0f) ? (1.0f / l_i[j]) : 0.0f;
        const size_t orow = (size_t)(b * 512 + qt * 128 + r0 + gid + j * 8);
        __half* op = out + orow * 2048 + h * 128 + tig * 2;
#pragma unroll
        for (int nt = 0; nt < 16; nt++) {
            *(__half2*)(op + nt * 8) =
                __floats2half2_rn(oacc[nt][j * 2] * inv, oacc[nt][j * 2 + 1] * inv);
        }
    }
}

// ============================================================================
extern "C" void kernel_launch(void* const* d_in, const int* in_sizes, int n_in,
                              void* d_out, int out_size)
{
    (void)in_sizes; (void)n_in; (void)out_size;
    const float* v     = (const float*)d_in[0];
    const float* q     = (const float*)d_in[1];
    const float* vmask = (const float*)d_in[2];
    const float* qmask = (const float*)d_in[3];
    const float* Wv    = (const float*)d_in[4];
    const float* bv    = (const float*)d_in[5];
    const float* Wq    = (const float*)d_in[6];
    const float* bq    = (const float*)d_in[7];
    const float* Wvo   = (const float*)d_in[8];
    const float* bvo   = (const float*)d_in[9];
    const float* Wqo   = (const float*)d_in[10];
    const float* bqo   = (const float*)d_in[11];

    float* out_v = (float*)d_out;
    float* out_q = out_v + (size_t)ROWS * OS_W;

    __half *vh, *qh, *Wvh, *Wqh, *Wvoh, *Wqoh, *vtrans, *qtrans, *vupd, *qupd;
    cudaGetSymbolAddress((void**)&vh,     gh_v);
    cudaGetSymbolAddress((void**)&qh,     gh_q);
    cudaGetSymbolAddress((void**)&Wvh,    gh_Wv);
    cudaGetSymbolAddress((void**)&Wqh,    gh_Wq);
    cudaGetSymbolAddress((void**)&Wvoh,   gh_Wvo);
    cudaGetSymbolAddress((void**)&Wqoh,   gh_Wqo);
    cudaGetSymbolAddress((void**)&vtrans, gh_vtrans);
    cudaGetSymbolAddress((void**)&qtrans, gh_qtrans);
    cudaGetSymbolAddress((void**)&vupd,   gh_vupd);
    cudaGetSymbolAddress((void**)&qupd,   gh_qupd);

    cudaFuncSetAttribute(attn_mma_kernel, cudaFuncAttributeMaxDynamicSharedMemorySize,
                         (int)sizeof(AttnSmem3));

    dim3 blk(256);

    // 0) all fp32 -> fp16 conversions in ONE launch
    f2h6_kernel<<<CONV_BLOCKS, blk>>>(v, q, Wv, Wq, Wvo, Wqo,
                                      vh, qh, Wvh, Wqh, Wvoh, Wqoh);

    // 1+2) fused: v_trans / q_trans
    {
        GemmArgs ga = { vh, nullptr, Wvh, nullptr, vtrans, bv, vmask, 2048, 0 };
        GemmArgs gb = { qh, nullptr, Wqh, nullptr, qtrans, bq, qmask, 1024, 0 };
        hgemm16_kernel<<<dim3(TRANS_W / BN, ROWS / BM, 2), blk>>>(ga, gb, TRANS_W);
    }

    // 3+4) fused bidirectional attention
    attn_mma_kernel<<<dim3(4, 32, 16), blk, sizeof(AttnSmem3)>>>(
        vtrans, qtrans, vmask, qmask, vupd, qupd);

    // 5+6) fused: updated_v / updated_q (concat GEMMs, fp32 out)
    {
        GemmArgs ga = { vh, vupd, Wvoh, out_v, nullptr, bvo, nullptr, 2048, 2048 };
        GemmArgs gb = { qh, qupd, Wqoh, out_q, nullptr, bqo, nullptr, 1024, 2048 };
        hgemm16_kernel<<<dim3(OS_W / BN, ROWS / BM, 2), blk>>>(ga, gb, OS_W);
    }
}

// round 16
// speedup vs baseline: 1.4858x; 1.1863x over previous
#include <cuda_runtime.h>
#include <cuda_fp16.h>
#include <math.h>

// Problem constants: B=16, N=M=512, VS=2048, QS=1024, OS=2048, H=16, DH=128
#define ROWS      8192
#define TRANS_W   6144
#define OS_W      2048

// -------------------- fp16 scratch (device globals; no allocations) --------
__device__ __half gh_v     [(size_t)ROWS * 2048];
__device__ __half gh_q     [(size_t)ROWS * 1024];
__device__ __half gh_Wv    [(size_t)2048 * TRANS_W];   // pair-interleaved u32
__device__ __half gh_Wq    [(size_t)1024 * TRANS_W];   // pair-interleaved u32
__device__ __half gh_Wvo   [(size_t)4096 * OS_W];      // pair-interleaved u32
__device__ __half gh_Wqo   [(size_t)3072 * OS_W];      // pair-interleaved u32
__device__ __half gh_vtrans[(size_t)ROWS * TRANS_W];
__device__ __half gh_qtrans[(size_t)ROWS * TRANS_W];
__device__ __half gh_vupd  [(size_t)ROWS * OS_W];
__device__ __half gh_qupd  [(size_t)ROWS * OS_W];

__device__ __forceinline__ unsigned pack_h2(float lo, float hi) {
    __half2 h = __floats2half2_rn(lo, hi);
    return *(unsigned*)&h;
}

__device__ __forceinline__ void mma_f16(float c[4], const unsigned a[4], const unsigned b[2]) {
    asm volatile(
        "mma.sync.aligned.m16n8k16.row.col.f32.f16.f16.f32 "
        "{%0,%1,%2,%3}, {%4,%5,%6,%7}, {%8,%9}, {%0,%1,%2,%3};\n"
        : "+f"(c[0]), "+f"(c[1]), "+f"(c[2]), "+f"(c[3])
        : "r"(a[0]), "r"(a[1]), "r"(a[2]), "r"(a[3]),
          "r"(b[0]), "r"(b[1]));
}

__device__ __forceinline__ void cp_async16(unsigned saddr, const void* gaddr) {
    asm volatile("cp.async.cg.shared.global [%0], [%1], 16;"
                 :: "r"(saddr), "l"(gaddr) : "memory");
}
__device__ __forceinline__ void cp_commit() {
    asm volatile("cp.async.commit_group;" ::: "memory");
}
__device__ __forceinline__ void cp_wait0() {
    asm volatile("cp.async.wait_group 0;" ::: "memory");
}

// ============================================================================
// prep: activations fp32->fp16 (one launch)
//   v 4194304 f4 | q 2097152 f4 ; total 6291456 = 24576 blocks x 256
// ============================================================================
#define FC0 4194304
#define F2H2_BLOCKS 24576
__global__ void __launch_bounds__(256)
f2h2_kernel(const float* __restrict__ s0, const float* __restrict__ s1,
            __half* __restrict__ d0, __half* __restrict__ d1)
{
    int i = blockIdx.x * blockDim.x + threadIdx.x;
    const float* s; __half* d; int j;
    if (i < FC0) { s = s0; d = d0; j = i; }
    else         { s = s1; d = d1; j = i - FC0; }
    float4 v = ((const float4*)s)[j];
    ((__half2*)d)[2 * j]     = __floats2half2_rn(v.x, v.y);
    ((__half2*)d)[2 * j + 1] = __floats2half2_rn(v.z, v.w);
}

// weight pack (R14-proven): src[Kr][N] fp32 -> dst pair-interleaved u32:
//   dst_u32[pr*N + c] = half2(src[2pr][c], src[2pr+1][c])
__global__ void __launch_bounds__(256)
wpack_kernel(const float* __restrict__ s, unsigned* __restrict__ d, int Kr, int N, int total)
{
    int i = blockIdx.x * blockDim.x + threadIdx.x;   // over (Kr/2)*(N/4)
    if (i >= total) return;
    int n4 = N >> 2;
    int pr = i / n4, c = (i - pr * n4) << 2;
    float4 lo = *(const float4*)(s + (size_t)(2 * pr)     * N + c);
    float4 hi = *(const float4*)(s + (size_t)(2 * pr + 1) * N + c);
    uint4 u = { pack_h2(lo.x, hi.x), pack_h2(lo.y, hi.y),
                pack_h2(lo.z, hi.z), pack_h2(lo.w, hi.w) };
    *(uint4*)(d + (size_t)pr * N + c) = u;
}

// ============================================================================
// FP16-in GEMM (fp32 accum), CTA 128x128, warp 64x32, BK=64 (4 k16 steps per
// barrier), double-buffered dynamic SMEM, dual-A concat, z-fused problems.
//   A: register prefetch (4 x uint4), As stride 36 (conflict-free frags/STS)
//   B: cp.async from pre-pair-interleaved weights, Bs stride 136
// ============================================================================
#define BM 128
#define BN 128
#define BK 64
#define ASTRIDE 36                      // 32 data u32 + 4 pad
#define BSTRIDE 136
#define AS_U32 (128 * ASTRIDE)          // 4608 per stage
#define BS_U32 (32 * BSTRIDE)           // 4352 per stage
#define BS_BASE (2 * AS_U32)            // 9216
#define GSM_U32 (2 * AS_U32 + 2 * BS_U32)   // 17920 u32 = 71680 B

struct GemmArgs {
    const __half* A1; const __half* A2; const unsigned* B;
    float* C32; __half* C16;
    const float* bias; const float* mask;
    int K1; int K2;
};

__global__ void __launch_bounds__(256, 2)
hgemm16_kernel(GemmArgs ga, GemmArgs gb, int N)
{
    extern __shared__ unsigned smemu[];
    const GemmArgs g = blockIdx.z ? gb : ga;
    const int K1 = g.K1, K2 = g.K2;
    const int K = K1 + K2;
    const int nCh = K / BK;

    const int tid  = threadIdx.x;
    const int lane = tid & 31;
    const int warp = tid >> 5;
    const int gid  = lane >> 2;
    const int tig  = lane & 3;
    const int wm = (warp >> 2) * 64;
    const int wn = (warp & 3) * 32;

    const int rowBase = blockIdx.y * BM;
    const int colBase = blockIdx.x * BN;

    // A staging: unit u = tid + i*256 (i<4): row u>>3 (0..127), slot u&7
    const int rA   = tid >> 3;            // 0..31, +32 per i
    const int slot = tid & 7;             // uint4 slot; half offset slot*8
    // B cp.async: unit u = tid + i*256: pair-row (tid>>5)+i*8, 4 u32 at (tid&31)*4
    const int prB = tid >> 5;
    const int cB  = (tid & 31) << 2;

    // A base pointers (dual segment) + row-block strides
    const __half* a1b = (K1 > 0) ? g.A1 + (size_t)(rowBase + rA) * K1 + slot * 8 : nullptr;
    const __half* a2b = (K2 > 0) ? g.A2 + (size_t)(rowBase + rA) * K2 - K1 + slot * 8 : nullptr;
    if (!a1b) a1b = a2b;
    if (!a2b) a2b = a1b;
    const size_t aStep1 = (size_t)32 * K1;
    const size_t aStep2 = (size_t)32 * K2;

    const unsigned* bBase = g.B + (size_t)prB * N + colBase + cB;   // + ck*32N + i*8N

    unsigned sbase;
    {
        unsigned long long t;
        asm("cvta.to.shared.u64 %0, %1;" : "=l"(t) : "l"((void*)smemu));
        sbase = (unsigned)t;
    }

    float acc[4][4][4];
#pragma unroll
    for (int i = 0; i < 4; i++)
#pragma unroll
        for (int j = 0; j < 4; j++)
#pragma unroll
            for (int r = 0; r < 4; r++) acc[i][j][r] = 0.0f;

    // ---- prologue: A(0) -> regs; cp.async B(0) ----
    uint4 ra[4];
    {
        const __half* ab   = (0 < K1) ? a1b : a2b;
        const size_t  astp = (0 < K1) ? aStep1 : aStep2;
#pragma unroll
        for (int i = 0; i < 4; i++)
            ra[i] = *(const uint4*)(ab + (size_t)i * astp);
#pragma unroll
        for (int i = 0; i < 4; i++)
            cp_async16(sbase + (unsigned)((BS_BASE + (prB + i * 8) * BSTRIDE + cB) * 4),
                       bBase + (size_t)(i * 8) * N);
        cp_commit();
    }

    for (int ck = 0; ck < nCh; ck++) {
        const int cur = ck & 1;

        // store A regs -> As[cur]
#pragma unroll
        for (int i = 0; i < 4; i++)
            *(uint4*)&smemu[cur * AS_U32 + (rA + i * 32) * ASTRIDE + slot * 4] = ra[i];

        cp_wait0();          // B(ck) resident
        __syncthreads();     // staging visible; WAR cleared for both buffers

        // overlap next-chunk loads with compute
        if (ck + 1 < nCh) {
            const int k0n = (ck + 1) * BK;
            const __half* ab   = (k0n < K1) ? a1b : a2b;
            const size_t  astp = (k0n < K1) ? aStep1 : aStep2;
#pragma unroll
            for (int i = 0; i < 4; i++)
                ra[i] = *(const uint4*)(ab + k0n + (size_t)i * astp);
            const unsigned* bsrc = bBase + (size_t)(ck + 1) * 32 * N;
            const unsigned bdst = sbase +
                (unsigned)((BS_BASE + (cur ^ 1) * BS_U32 + prB * BSTRIDE + cB) * 4);
#pragma unroll
            for (int i = 0; i < 4; i++)
                cp_async16(bdst + (unsigned)(i * 8 * BSTRIDE * 4),
                           bsrc + (size_t)(i * 8) * N);
            cp_commit();
        }

        // compute: four k16 steps, 16 MMAs each
#pragma unroll
        for (int ks = 0; ks < 4; ks++) {
            const int o = ks * 8;
            unsigned afr[4][4];
#pragma unroll
            for (int mt = 0; mt < 4; mt++) {
                const int r = wm + mt * 16 + gid;
                afr[mt][0] = smemu[cur * AS_U32 + r * ASTRIDE + o + tig];
                afr[mt][1] = smemu[cur * AS_U32 + (r + 8) * ASTRIDE + o + tig];
                afr[mt][2] = smemu[cur * AS_U32 + r * ASTRIDE + o + tig + 4];
                afr[mt][3] = smemu[cur * AS_U32 + (r + 8) * ASTRIDE + o + tig + 4];
            }
            unsigned bfr[4][2];
#pragma unroll
            for (int nt = 0; nt < 4; nt++) {
                const int c = wn + nt * 8 + gid;
                bfr[nt][0] = smemu[BS_BASE + cur * BS_U32 + (o + tig) * BSTRIDE + c];
                bfr[nt][1] = smemu[BS_BASE + cur * BS_U32 + (o + tig + 4) * BSTRIDE + c];
            }
#pragma unroll
            for (int mt = 0; mt < 4; mt++)
#pragma unroll
                for (int nt = 0; nt < 4; nt++)
                    mma_f16(acc[mt][nt], afr[mt], bfr[nt]);
        }
    }

    // ---- epilogue: relu(x + bias[col]) * mask[row]; fp16 or fp32 out ----
#pragma unroll
    for (int mt = 0; mt < 4; mt++) {
        const int r0 = rowBase + wm + mt * 16 + gid;
        const int r1 = r0 + 8;
        const float m0 = g.mask ? g.mask[r0] : 1.0f;
        const float m1 = g.mask ? g.mask[r1] : 1.0f;
#pragma unroll
        for (int nt = 0; nt < 4; nt++) {
            const int c = colBase + wn + nt * 8 + (tig << 1);
            const float b0 = g.bias[c], b1 = g.bias[c + 1];
            float v00 = fmaxf(acc[mt][nt][0] + b0, 0.0f) * m0;
            float v01 = fmaxf(acc[mt][nt][1] + b1, 0.0f) * m0;
            float v10 = fmaxf(acc[mt][nt][2] + b0, 0.0f) * m1;
            float v11 = fmaxf(acc[mt][nt][3] + b1, 0.0f) * m1;
            if (g.C16) {
                *(__half2*)(g.C16 + (size_t)r0 * N + c) = __floats2half2_rn(v00, v01);
                *(__half2*)(g.C16 + (size_t)r1 * N + c) = __floats2half2_rn(v10, v11);
            } else {
                float2 a = { v00, v01 }, b = { v10, v11 };
                *(float2*)(g.C32 + (size_t)r0 * N + c) = a;
                *(float2*)(g.C32 + (size_t)r1 * N + c) = b;
            }
        }
    }
}

// ============================================================================
// FP16 tensor-core flash attention — unchanged from R15 (passing); both
// directions fused via blockIdx.y in [0,32): dir = y>>4, h = y&15.
// ============================================================================
struct AttnSmem3 {
    unsigned Qh[128][68];
    unsigned Kh[64][68];
    unsigned Vh[32][136];
    unsigned Ps[128][36];
    float    Mk[64];
};

__global__ void __launch_bounds__(256)
attn_mma_kernel(const __half* __restrict__ vtrans, const __half* __restrict__ qtrans,
                const float* __restrict__ vmask, const float* __restrict__ qmask,
                __half* __restrict__ vupd, __half* __restrict__ qupd)
{
    extern __shared__ char smem_raw[];
    AttnSmem3& sm = *reinterpret_cast<AttnSmem3*>(smem_raw);

    const int b   = blockIdx.z;
    const int hd  = blockIdx.y;
    const int dir = hd >> 4;
    const int h   = hd & 15;
    const int qt  = blockIdx.x;

    const __half* Tq    = dir ? qtrans : vtrans;
    const __half* Tk    = dir ? vtrans : qtrans;
    const float*  maskK = dir ? vmask  : qmask;
    __half*       out   = dir ? qupd   : vupd;

    const int tid  = threadIdx.x;
    const int lane = tid & 31;
    const int warp = tid >> 5;
    const int r0   = warp * 16;
    const int gid  = lane >> 2;
    const int tig  = lane & 3;
    const float SCALE = 0.08838834764831845f;

    const __half* qbase = Tq + (size_t)(b * 512 + qt * 128) * 6144 + 2048 + h * 128;
#pragma unroll
    for (int it = 0; it < 8; it++) {
        int lin = it * 256 + tid;
        int r = lin >> 4, cu = (lin & 15) << 2;
        uint4 u = *(const uint4*)(qbase + (size_t)r * 6144 + cu * 2);
        *(uint4*)&sm.Qh[r][cu] = u;
    }

    float m_i[2] = { -INFINITY, -INFINITY };
    float l_i[2] = { 0.0f, 0.0f };
    float oacc[16][4];
#pragma unroll
    for (int nt = 0; nt < 16; nt++)
#pragma unroll
        for (int j = 0; j < 4; j++) oacc[nt][j] = 0.0f;

    const __half* kbase = Tk + (size_t)b * 512 * 6144 + h * 128;
    const __half* vbase = kbase + 4096;

    const int vpr = tid >> 5;
    const int vc0 = (tid & 31) << 2;

    for (int kt = 0; kt < 8; kt++) {
        __syncthreads();
#pragma unroll
        for (int it = 0; it < 4; it++) {
            int lin = it * 256 + tid;
            int r = lin >> 4, cu = (lin & 15) << 2;
            uint4 u = *(const uint4*)(kbase + (size_t)(kt * 64 + r) * 6144 + cu * 2);
            *(uint4*)&sm.Kh[r][cu] = u;
        }
#pragma unroll
        for (int it = 0; it < 4; it++) {
            int p = it * 8 + vpr;
            uint2 lo = *(const uint2*)(vbase + (size_t)(kt * 64 + 2 * p)     * 6144 + vc0);
            uint2 hi = *(const uint2*)(vbase + (size_t)(kt * 64 + 2 * p + 1) * 6144 + vc0);
            uint4 u;
            u.x = __byte_perm(lo.x, hi.x, 0x5410);
            u.y = __byte_perm(lo.x, hi.x, 0x7632);
            u.z = __byte_perm(lo.y, hi.y, 0x5410);
            u.w = __byte_perm(lo.y, hi.y, 0x7632);
            *(uint4*)&sm.Vh[p][vc0] = u;
        }
        if (tid < 64) sm.Mk[tid] = maskK[b * 512 + kt * 64 + tid];
        __syncthreads();

        float c[8][4];
#pragma unroll
        for (int nt = 0; nt < 8; nt++)
#pragma unroll
            for (int j = 0; j < 4; j++) c[nt][j] = 0.0f;

#pragma unroll
        for (int ks = 0; ks < 8; ks++) {
            const int pd = ks * 8 + tig;
            unsigned a[4];
            a[0] = sm.Qh[r0 + gid][pd];
            a[1] = sm.Qh[r0 + gid + 8][pd];
            a[2] = sm.Qh[r0 + gid][pd + 4];
            a[3] = sm.Qh[r0 + gid + 8][pd + 4];
#pragma unroll
            for (int nt = 0; nt < 8; nt++) {
                unsigned bf[2];
                bf[0] = sm.Kh[nt * 8 + gid][pd];
                bf[1] = sm.Kh[nt * 8 + gid][pd + 4];
                mma_f16(c[nt], a, bf);
            }
        }

#pragma unroll
        for (int nt = 0; nt < 8; nt++) {
            const int col = nt * 8 + tig * 2;
            const float k0m = sm.Mk[col];
            const float k1m = sm.Mk[col + 1];
            c[nt][0] = (k0m != 0.0f) ? c[nt][0] * SCALE : -INFINITY;
            c[nt][1] = (k1m != 0.0f) ? c[nt][1] * SCALE : -INFINITY;
            c[nt][2] = (k0m != 0.0f) ? c[nt][2] * SCALE : -INFINITY;
            c[nt][3] = (k1m != 0.0f) ? c[nt][3] * SCALE : -INFINITY;
        }

#pragma unroll
        for (int j = 0; j < 2; j++) {
            float tmax = -INFINITY;
#pragma unroll
            for (int nt = 0; nt < 8; nt++)
                tmax = fmaxf(tmax, fmaxf(c[nt][j * 2], c[nt][j * 2 + 1]));
            tmax = fmaxf(tmax, __shfl_xor_sync(0xffffffffu, tmax, 1));
            tmax = fmaxf(tmax, __shfl_xor_sync(0xffffffffu, tmax, 2));
            float mnew  = fmaxf(m_i[j], tmax);
            float msafe = (mnew == -INFINITY) ? 0.0f : mnew;
            float corr  = __expf(m_i[j] - msafe);
            float lsum = 0.0f;
            const int row = r0 + gid + j * 8;
#pragma unroll
            for (int nt = 0; nt < 8; nt++) {
                float p0 = __expf(c[nt][j * 2]     - msafe);
                float p1 = __expf(c[nt][j * 2 + 1] - msafe);
                lsum += p0 + p1;
                sm.Ps[row][nt * 4 + tig] = pack_h2(p0, p1);
            }
            lsum += __shfl_xor_sync(0xffffffffu, lsum, 1);
            lsum += __shfl_xor_sync(0xffffffffu, lsum, 2);
            l_i[j] = l_i[j] * corr + lsum;
            m_i[j] = mnew;
#pragma unroll
            for (int nt = 0; nt < 16; nt++) {
                oacc[nt][j * 2]     *= corr;
                oacc[nt][j * 2 + 1] *= corr;
            }
        }
        __syncwarp();

#pragma unroll
        for (int ks = 0; ks < 4; ks++) {
            const int pk = ks * 8 + tig;
            unsigned a[4];
            a[0] = sm.Ps[r0 + gid][pk];
            a[1] = sm.Ps[r0 + gid + 8][pk];
            a[2] = sm.Ps[r0 + gid][pk + 4];
            a[3] = sm.Ps[r0 + gid + 8][pk + 4];
#pragma unroll
            for (int nt = 0; nt < 16; nt++) {
                unsigned bf[2];
                bf[0] = sm.Vh[ks * 8 + tig][nt * 8 + gid];
                bf[1] = sm.Vh[ks * 8 + tig + 4][nt * 8 + gid];
                mma_f16(oacc[nt], a, bf);
            }
        }
    }

#pragma unroll
    for (int j = 0; j < 2; j++) {
        const float inv = (l_i[j] > 0.0f) ? (1.0f / l_i[j]) : 0.0f;
        const size_t orow = (size_t)(b * 512 + qt * 128 + r0 + gid + j * 8);
        __half* op = out + orow * 2048 + h * 128 + tig * 2;
#pragma unroll
        for (int nt = 0; nt < 16; nt++) {
            *(__half2*)(op + nt * 8) =
                __floats2half2_rn(oacc[nt][j * 2] * inv, oacc[nt][j * 2 + 1] * inv);
        }
    }
}

// ============================================================================
extern "C" void kernel_launch(void* const* d_in, const int* in_sizes, int n_in,
                              void* d_out, int out_size)
{
    (void)in_sizes; (void)n_in; (void)out_size;
    const float* v     = (const float*)d_in[0];
    const float* q     = (const float*)d_in[1];
    const float* vmask = (const float*)d_in[2];
    const float* qmask = (const float*)d_in[3];
    const float* Wv    = (const float*)d_in[4];
    const float* bv    = (const float*)d_in[5];
    const float* Wq    = (const float*)d_in[6];
    const float* bq    = (const float*)d_in[7];
    const float* Wvo   = (const float*)d_in[8];
    const float* bvo   = (const float*)d_in[9];
    const float* Wqo   = (const float*)d_in[10];
    const float* bqo   = (const float*)d_in[11];

    float* out_v = (float*)d_out;
    float* out_q = out_v + (size_t)ROWS * OS_W;

    __half *vh, *qh, *Wvh, *Wqh, *Wvoh, *Wqoh, *vtrans, *qtrans, *vupd, *qupd;
    cudaGetSymbolAddress((void**)&vh,     gh_v);
    cudaGetSymbolAddress((void**)&qh,     gh_q);
    cudaGetSymbolAddress((void**)&Wvh,    gh_Wv);
    cudaGetSymbolAddress((void**)&Wqh,    gh_Wq);
    cudaGetSymbolAddress((void**)&Wvoh,   gh_Wvo);
    cudaGetSymbolAddress((void**)&Wqoh,   gh_Wqo);
    cudaGetSymbolAddress((void**)&vtrans, gh_vtrans);
    cudaGetSymbolAddress((void**)&qtrans, gh_qtrans);
    cudaGetSymbolAddress((void**)&vupd,   gh_vupd);
    cudaGetSymbolAddress((void**)&qupd,   gh_qupd);

    cudaFuncSetAttribute(attn_mma_kernel, cudaFuncAttributeMaxDynamicSharedMemorySize,
                         (int)sizeof(AttnSmem3));
    cudaFuncSetAttribute(hgemm16_kernel, cudaFuncAttributeMaxDynamicSharedMemorySize,
                         GSM_U32 * 4);

    dim3 blk(256);

    // 0) activations fp32->fp16 + weight pair-interleave packs
    f2h2_kernel<<<F2H2_BLOCKS, blk>>>(v, q, vh, qh);
    wpack_kernel<<<6144, blk>>>(Wv,  (unsigned*)Wvh,  2048, TRANS_W, 1024 * (TRANS_W / 4));
    wpack_kernel<<<3072, blk>>>(Wq,  (unsigned*)Wqh,  1024, TRANS_W,  512 * (TRANS_W / 4));
    wpack_kernel<<<4096, blk>>>(Wvo, (unsigned*)Wvoh, 4096, OS_W,    2048 * (OS_W / 4));
    wpack_kernel<<<3072, blk>>>(Wqo, (unsigned*)Wqoh, 3072, OS_W,    1536 * (OS_W / 4));

    // 1+2) fused: v_trans / q_trans
    {
        GemmArgs ga = { vh, nullptr, (const unsigned*)Wvh, nullptr, vtrans, bv, vmask, 2048, 0 };
        GemmArgs gb = { qh, nullptr, (const unsigned*)Wqh, nullptr, qtrans, bq, qmask, 1024, 0 };
        hgemm16_kernel<<<dim3(TRANS_W / BN, ROWS / BM, 2), blk, GSM_U32 * 4>>>(ga, gb, TRANS_W);
    }

    // 3+4) fused bidirectional attention
    attn_mma_kernel<<<dim3(4, 32, 16), blk, sizeof(AttnSmem3)>>>(
        vtrans, qtrans, vmask, qmask, vupd, qupd);

    // 5+6) fused: updated_v / updated_q (concat GEMMs, fp32 out)
    {
        GemmArgs ga = { vh, vupd, (const unsigned*)Wvoh, out_v, nullptr, bvo, nullptr, 2048, 2048 };
        GemmArgs gb = { qh, qupd, (const unsigned*)Wqoh, out_q, nullptr, bqo, nullptr, 1024, 2048 };
        hgemm16_kernel<<<dim3(OS_W / BN, ROWS / BM, 2), blk, GSM_U32 * 4>>>(ga, gb, OS_W);
    }
}